// round 2
// baseline (speedup 1.0000x reference)
#include <cuda_runtime.h>
#include <cuda_bf16.h>
#include <cstdint>

// ---------------------------------------------------------------------------
// Problem constants
// ---------------------------------------------------------------------------
#define Bb   8
#define HIN  256
#define WIN  256
#define H2   128
#define W2   128
#define Nn   16
#define Mm   32
#define Ss   128
#define Tt   (Bb*H2*W2)          // 131072 tokens
#define ALPHA 1e-6f

// ---------------------------------------------------------------------------
// Scratch buffers (static device globals; no cudaMalloc allowed)
// ---------------------------------------------------------------------------
__device__ float g_a1n [Bb*Nn*HIN*WIN];     //  33.5 MB silu(conv1_n)
__device__ float g_a1s [(size_t)Bb*Ss*HIN*WIN]; // 268 MB silu(conv1_s)
__device__ float g_z   [(size_t)Tt*Nn];     //   8.4 MB tokens z
__device__ float g_ts  [(size_t)Tt*Ss];     //  67  MB tokens t_star
__device__ float g_w   [(size_t)Tt*Mm];     //  16.8MB softmax weights
__device__ float g_part[(size_t)1024*32*160]; // 21 MB block partials (G|U)
__device__ float g_gu  [32*160];            // reduced [G | U]
__device__ float g_vnew[Mm*Ss];             // updated cell_v
__device__ float g_d0m [(size_t)Bb*Ss*H2*W2]; // 67 MB decoder input NCHW
__device__ float g_dec [(size_t)Bb*3*HIN*WIN]; // 6.3 MB silu(deconv)

// ---------------------------------------------------------------------------
// Generic fused conv3x3 + bias + SiLU.  pad=1, stride in {1,2}.
// Block = 256 threads -> 16x16 output tile, COG output channels per block.
// Weights of the channel group staged in smem; inner loop is FFMA-dominated
// with broadcast weight LDS (keeps fma pipe ~full on sm_103a).
// ---------------------------------------------------------------------------
template<int CIN, int OUTC, int COG, int STRIDE, bool TOKEN_OUT>
__global__ void __launch_bounds__(256) conv3x3(
    const float* __restrict__ in, const float* __restrict__ wgt,
    const float* __restrict__ bias, float* __restrict__ out,
    int Hin, int Win, int Ho, int Wo)
{
    constexpr int ITD = 15*STRIDE + 3;           // input tile edge (18 or 33)
    __shared__ float sW[COG*CIN*9];
    __shared__ float sIn[ITD*ITD];

    const int tid = threadIdx.x;
    const int groups = OUTC / COG;
    const int b  = blockIdx.z / groups;
    const int cg = blockIdx.z % groups;
    const int cbase = cg * COG;

    // stage weights for this output-channel group (layout identical to global)
    for (int i = tid; i < COG*CIN*9; i += 256)
        sW[i] = wgt[(size_t)cbase*CIN*9 + i];

    const int ty = tid >> 4, tx = tid & 15;
    const int oy = blockIdx.y*16 + ty;
    const int ox = blockIdx.x*16 + tx;

    float acc[COG];
#pragma unroll
    for (int c = 0; c < COG; c++) acc[c] = 0.f;

    const float* inb = in + (size_t)b * CIN * Hin * Win;
    const int iy0 = blockIdx.y*16*STRIDE - 1;
    const int ix0 = blockIdx.x*16*STRIDE - 1;
    const int base = (ty*STRIDE)*ITD + tx*STRIDE;

    for (int cin = 0; cin < CIN; cin++) {
        __syncthreads();
        const float* ic = inb + (size_t)cin * Hin * Win;
        for (int i = tid; i < ITD*ITD; i += 256) {
            int r = i / ITD, cc = i - r*ITD;
            int ih = iy0 + r, iw = ix0 + cc;
            float v = 0.f;
            if ((unsigned)ih < (unsigned)Hin && (unsigned)iw < (unsigned)Win)
                v = ic[ih*Win + iw];
            sIn[i] = v;
        }
        __syncthreads();
        const float* wp = sW + cin*9;
#pragma unroll
        for (int dy = 0; dy < 3; dy++)
#pragma unroll
            for (int dx = 0; dx < 3; dx++) {
                float iv = sIn[base + dy*ITD + dx];
#pragma unroll
                for (int c = 0; c < COG; c++)
                    acc[c] += iv * wp[c*CIN*9 + dy*3 + dx];
            }
    }

#pragma unroll
    for (int c = 0; c < COG; c++) {
        float v = acc[c] + bias[cbase + c];
        v = v / (1.f + __expf(-v));                 // SiLU
        if (TOKEN_OUT) {
            size_t t = ((size_t)b*Ho + oy)*Wo + ox;
            out[t*OUTC + cbase + c] = v;
        } else {
            out[(((size_t)b*OUTC + cbase + c)*Ho + oy)*Wo + ox] = v;
        }
    }
}

// ---------------------------------------------------------------------------
// Memcell pass 1: w = softmax(z @ K^T / 4) per token. One thread per token.
// ---------------------------------------------------------------------------
__global__ void __launch_bounds__(256) memcell_softmax(
    const float* __restrict__ z, const float* __restrict__ ck,
    float* __restrict__ wout)
{
    __shared__ float sK[Mm*Nn];                // 32x16
    const int tid = threadIdx.x;
    for (int i = tid; i < Mm*Nn; i += 256) sK[i] = ck[i];
    __syncthreads();

    const int t = blockIdx.x*256 + tid;
    const float4* zp = (const float4*)(z + (size_t)t*Nn);
    float4 z0 = zp[0], z1 = zp[1], z2 = zp[2], z3 = zp[3];

    float s[Mm];
    float mx = -1e30f;
#pragma unroll
    for (int m = 0; m < Mm; m++) {
        const float* k = sK + m*Nn;
        float d = z0.x*k[0] + z0.y*k[1] + z0.z*k[2] + z0.w*k[3]
                + z1.x*k[4] + z1.y*k[5] + z1.z*k[6] + z1.w*k[7]
                + z2.x*k[8] + z2.y*k[9] + z2.z*k[10]+ z2.w*k[11]
                + z3.x*k[12]+ z3.y*k[13]+ z3.z*k[14]+ z3.w*k[15];
        d *= 0.25f;                              // / sqrt(16)
        s[m] = d;
        mx = fmaxf(mx, d);
    }
    float sum = 0.f;
#pragma unroll
    for (int m = 0; m < Mm; m++) { s[m] = __expf(s[m]-mx); sum += s[m]; }
    float inv = 1.f / sum;
    float4* wo = (float4*)(wout + (size_t)t*Mm);
#pragma unroll
    for (int j = 0; j < Mm/4; j++) {
        float4 v; v.x = s[4*j]*inv; v.y = s[4*j+1]*inv;
        v.z = s[4*j+2]*inv; v.w = s[4*j+3]*inv;
        wo[j] = v;
    }
}

// ---------------------------------------------------------------------------
// Memcell pass 2: block-partial accumulation of A = [G | U] where
//   G = W^T W  (32x32),  U = W^T t_star  (32x128)   -> cols j in [0,160)
// Grid 1024 blocks x 128 tokens each. Thread owns a 4x5 register tile.
// ---------------------------------------------------------------------------
__global__ void __launch_bounds__(256) memcell_outer(
    const float* __restrict__ wmat, const float* __restrict__ ts,
    float* __restrict__ part)
{
    __shared__ float sv[8*160];                  // 8 staged tokens of [w|t*]
    const int tid = threadIdx.x;
    const int ti = tid >> 5;                     // 0..7 -> rows ti*4..+3
    const int tj = tid & 31;                     // 0..31 -> cols tj*5..+4
    float acc[4][5];
#pragma unroll
    for (int a = 0; a < 4; a++)
#pragma unroll
        for (int q = 0; q < 5; q++) acc[a][q] = 0.f;

    const int tokb = blockIdx.x * 128;
    for (int ch = 0; ch < 128; ch += 8) {
        __syncthreads();
#pragma unroll
        for (int l = 0; l < 5; l++) {
            int idx = l*256 + tid;               // 0..1279
            int tk = idx / 160, f = idx - tk*160;
            int t = tokb + ch + tk;
            sv[tk*160 + f] = (f < 32) ? wmat[(size_t)t*32 + f]
                                      : ts[(size_t)t*128 + (f-32)];
        }
        __syncthreads();
#pragma unroll
        for (int tk = 0; tk < 8; tk++) {
            float wi[4], vj[5];
#pragma unroll
            for (int a = 0; a < 4; a++) wi[a] = sv[tk*160 + ti*4 + a];
#pragma unroll
            for (int q = 0; q < 5; q++) vj[q] = sv[tk*160 + tj*5 + q];
#pragma unroll
            for (int a = 0; a < 4; a++)
#pragma unroll
                for (int q = 0; q < 5; q++) acc[a][q] += wi[a]*vj[q];
        }
    }
    float* pp = part + (size_t)blockIdx.x * 5120;
#pragma unroll
    for (int a = 0; a < 4; a++)
#pragma unroll
        for (int q = 0; q < 5; q++)
            pp[(ti*4+a)*160 + tj*5 + q] = acc[a][q];
}

// Deterministic fixed-order reduction of the 1024 block partials.
__global__ void __launch_bounds__(256) reduce_partials(
    const float* __restrict__ part, float* __restrict__ gu)
{
    int cell = blockIdx.x*256 + threadIdx.x;     // 5120 cells
    float s = 0.f;
#pragma unroll 8
    for (int p = 0; p < 1024; p++) s += part[(size_t)p*5120 + cell];
    gu[cell] = s;
}

// cell_v_new = V + alpha * (U - G @ V).   Single block.
__global__ void __launch_bounds__(256) cell_update(
    const float* __restrict__ gu, const float* __restrict__ cv,
    float* __restrict__ vnew)
{
    __shared__ float sG[Mm*Mm];
    __shared__ float sV[Mm*Ss];
    const int tid = threadIdx.x;
    for (int i = tid; i < Mm*Mm; i += 256) {
        int m = i >> 5, j = i & 31;
        sG[i] = gu[m*160 + j];
    }
    for (int i = tid; i < Mm*Ss; i += 256) sV[i] = cv[i];
    __syncthreads();
    for (int k = 0; k < 16; k++) {
        int cell = k*256 + tid;                  // 4096 cells
        int m = cell >> 7, s0 = cell & 127;
        float d = gu[m*160 + 32 + s0];           // U[m][s]
#pragma unroll
        for (int mp = 0; mp < Mm; mp++) d -= sG[m*32 + mp] * sV[mp*128 + s0];
        vnew[cell] = sV[cell] + ALPHA * d;
    }
}

// ---------------------------------------------------------------------------
// Memcell pass 3: t_read = W @ cell_v_new, written NCHW [B,S,H2,W2].
// Block = 64 consecutive tokens (same b,h). Warp w handles channels w*16..+15,
// lanes handle tokens (lane, lane+32). Coalesced NCHW stores.
// ---------------------------------------------------------------------------
__global__ void __launch_bounds__(256) memcell_read(
    const float* __restrict__ wmat, const float* __restrict__ vnew,
    float* __restrict__ d0m)
{
    __shared__ float sV[Mm*Ss];                  // 16 KB
    __shared__ float sW[64*33];                  // padded stride 33
    const int tid = threadIdx.x;
    for (int i = tid; i < Mm*Ss; i += 256) sV[i] = vnew[i];
    const int tbase = blockIdx.x * 64;
    for (int i = tid; i < 64*32; i += 256) {
        int tk = i >> 5, m = i & 31;
        sW[tk*33 + m] = wmat[(size_t)(tbase + tk)*32 + m];
    }
    __syncthreads();

    const int lane = tid & 31, wid = tid >> 5;
    const int cb = wid * 16;
    float a0[16], a1[16];
#pragma unroll
    for (int c = 0; c < 16; c++) { a0[c] = 0.f; a1[c] = 0.f; }

    const float* w0 = sW + lane*33;
    const float* w1 = sW + (lane + 32)*33;
#pragma unroll 4
    for (int m = 0; m < Mm; m++) {
        float x0 = w0[m], x1 = w1[m];
        const float* vv = sV + m*128 + cb;
#pragma unroll
        for (int c = 0; c < 16; c++) {
            float v = vv[c];
            a0[c] += x0 * v;
            a1[c] += x1 * v;
        }
    }
    const int b = tbase >> 14;
    const int rem = tbase & 16383;
    const int h = rem >> 7;
    const int wc = rem & 127;
    size_t obase = ((size_t)b*Ss)*((size_t)H2*W2) + (size_t)h*W2 + wc;
#pragma unroll
    for (int c = 0; c < 16; c++) {
        size_t o = obase + (size_t)(cb + c)*(H2*W2);
        d0m[o + lane]      = a0[c];
        d0m[o + 32 + lane] = a1[c];
    }
}

// ---------------------------------------------------------------------------
// ConvTranspose2d(S=128 -> 3, k=4, s=2, p=1) + bias + SiLU.
// out[b,o,y,x] = sum_i sum_{2x2 taps} in[b,i,h,w]*Wd[i,o,ky,kx], y=2h+ky-1.
// Whole weight tensor (6144 f32 = 24 KB) staged in smem.
// ---------------------------------------------------------------------------
__global__ void __launch_bounds__(256) deconv_kernel(
    const float* __restrict__ in, const float* __restrict__ dw,
    const float* __restrict__ db, float* __restrict__ out)
{
    __shared__ float sWd[Ss*3*16];               // [cin][o][ky*4+kx]
    __shared__ float sIn[8*100];                 // 8 cins x 10x10 input tile
    const int tid = threadIdx.x;
    for (int i = tid; i < Ss*3*16; i += 256) sWd[i] = dw[i];

    const int b  = blockIdx.z;
    const int Y0 = blockIdx.y*16, X0 = blockIdx.x*16;
    const int ty = tid >> 4, tx = tid & 15;
    const int y = Y0 + ty, x = X0 + tx;
    const int hb = (Y0 >> 1) - 1, wb = (X0 >> 1) - 1;

    const int py = (y + 1) & 1, px = (x + 1) & 1;
    const int hs0 = ((y + 1 - py) >> 1) - hb;    // 1..9
    const int ws0 = ((x + 1 - px) >> 1) - wb;

    float acc[3] = {0.f, 0.f, 0.f};
    const float* inb = in + (size_t)b * Ss * H2 * W2;

    for (int c0 = 0; c0 < Ss; c0 += 8) {
        __syncthreads();
        for (int i = tid; i < 800; i += 256) {
            int c = i / 100, rr = i - c*100;
            int r = rr / 10, cc = rr - r*10;
            int h = hb + r, w = wb + cc;
            float v = 0.f;
            if ((unsigned)h < (unsigned)H2 && (unsigned)w < (unsigned)W2)
                v = inb[((size_t)(c0 + c)*H2 + h)*W2 + w];
            sIn[c*100 + rr] = v;
        }
        __syncthreads();
#pragma unroll
        for (int c = 0; c < 8; c++) {
            float i00 = sIn[c*100 + hs0*10 + ws0];
            float i01 = sIn[c*100 + hs0*10 + ws0 - 1];
            float i10 = sIn[c*100 + (hs0-1)*10 + ws0];
            float i11 = sIn[c*100 + (hs0-1)*10 + ws0 - 1];
            const float* w8 = sWd + (c0 + c)*48;
#pragma unroll
            for (int o = 0; o < 3; o++) {
                const float* wo = w8 + o*16;
                acc[o] += i00 * wo[py*4 + px]
                        + i01 * wo[py*4 + px + 2]
                        + i10 * wo[(py+2)*4 + px]
                        + i11 * wo[(py+2)*4 + px + 2];
            }
        }
    }
#pragma unroll
    for (int o = 0; o < 3; o++) {
        float v = acc[o] + db[o];
        v = v / (1.f + __expf(-v));
        out[(((size_t)b*3 + o)*HIN + y)*WIN + x] = v;
    }
}

// ---------------------------------------------------------------------------
// Launch sequence
// ---------------------------------------------------------------------------
extern "C" void kernel_launch(void* const* d_in, const int* in_sizes, int n_in,
                              void* d_out, int out_size)
{
    const float* x      = (const float*)d_in[0];
    const float* e0n_w1 = (const float*)d_in[1];
    const float* e0n_b1 = (const float*)d_in[2];
    const float* e0n_w2 = (const float*)d_in[3];
    const float* e0n_b2 = (const float*)d_in[4];
    const float* e0s_w1 = (const float*)d_in[5];
    const float* e0s_b1 = (const float*)d_in[6];
    const float* e0s_w2 = (const float*)d_in[7];
    const float* e0s_b2 = (const float*)d_in[8];
    const float* d0_dw  = (const float*)d_in[9];
    const float* d0_db  = (const float*)d_in[10];
    const float* d0_cw  = (const float*)d_in[11];
    const float* d0_cb  = (const float*)d_in[12];
    const float* cell_k = (const float*)d_in[13];
    const float* cell_v = (const float*)d_in[14];
    float* outp = (float*)d_out;

    void *p_a1n, *p_a1s, *p_z, *p_ts, *p_w, *p_part, *p_gu, *p_vnew, *p_d0m, *p_dec;
    cudaGetSymbolAddress(&p_a1n, g_a1n);
    cudaGetSymbolAddress(&p_a1s, g_a1s);
    cudaGetSymbolAddress(&p_z,   g_z);
    cudaGetSymbolAddress(&p_ts,  g_ts);
    cudaGetSymbolAddress(&p_w,   g_w);
    cudaGetSymbolAddress(&p_part,g_part);
    cudaGetSymbolAddress(&p_gu,  g_gu);
    cudaGetSymbolAddress(&p_vnew,g_vnew);
    cudaGetSymbolAddress(&p_d0m, g_d0m);
    cudaGetSymbolAddress(&p_dec, g_dec);

    // Encoders
    conv3x3<3,16,16,1,false><<<dim3(16,16,Bb),256>>>(
        x, e0n_w1, e0n_b1, (float*)p_a1n, HIN, WIN, HIN, WIN);
    conv3x3<3,128,16,1,false><<<dim3(16,16,Bb*8),256>>>(
        x, e0s_w1, e0s_b1, (float*)p_a1s, HIN, WIN, HIN, WIN);
    conv3x3<16,16,16,2,true><<<dim3(8,8,Bb),256>>>(
        (const float*)p_a1n, e0n_w2, e0n_b2, (float*)p_z, HIN, WIN, H2, W2);
    conv3x3<128,128,8,2,true><<<dim3(8,8,Bb*16),256>>>(
        (const float*)p_a1s, e0s_w2, e0s_b2, (float*)p_ts, HIN, WIN, H2, W2);

    // Memcell
    memcell_softmax<<<Tt/256,256>>>((const float*)p_z, cell_k, (float*)p_w);
    memcell_outer<<<1024,256>>>((const float*)p_w, (const float*)p_ts, (float*)p_part);
    reduce_partials<<<20,256>>>((const float*)p_part, (float*)p_gu);
    cell_update<<<1,256>>>((const float*)p_gu, cell_v, (float*)p_vnew);
    memcell_read<<<Tt/64,256>>>((const float*)p_w, (const float*)p_vnew, (float*)p_d0m);

    // Decoder
    deconv_kernel<<<dim3(16,16,Bb),256>>>(
        (const float*)p_d0m, d0_dw, d0_db, (float*)p_dec);
    conv3x3<3,3,3,1,false><<<dim3(16,16,Bb),256>>>(
        (const float*)p_dec, d0_cw, d0_cb, outp, HIN, WIN, HIN, WIN);
}

// round 3
// speedup vs baseline: 2.0480x; 2.0480x over previous
#include <cuda_runtime.h>
#include <cuda_bf16.h>
#include <cstdint>

// ---------------------------------------------------------------------------
// Problem constants
// ---------------------------------------------------------------------------
#define Bb   8
#define HIN  256
#define WIN  256
#define H2   128
#define W2   128
#define Nn   16
#define Mm   32
#define Ss   128
#define Tt   (Bb*H2*W2)          // 131072 tokens
#define ALPHA 1e-6f

// ---------------------------------------------------------------------------
// Scratch buffers (static device globals; no cudaMalloc allowed)
// ---------------------------------------------------------------------------
__device__ float g_a1n [Bb*Nn*HIN*WIN];
__device__ float g_a1s [(size_t)Bb*Ss*HIN*WIN];
__device__ float g_z   [(size_t)Tt*Nn];
__device__ float g_ts  [(size_t)Tt*Ss];
__device__ float g_w   [(size_t)Tt*Mm];
__device__ float g_part[(size_t)1024*32*160];
__device__ float g_gu  [32*160];
__device__ float g_vnew[Mm*Ss];
__device__ float g_d0m [(size_t)Bb*Ss*H2*W2];
__device__ float g_dec [(size_t)Bb*3*HIN*WIN];

// ---------------------------------------------------------------------------
// Fast fused conv3x3 + bias + SiLU.  pad=1, stride in {1,2}.
// 256 threads -> 32x32 output tile; each thread: 4 x-pixels x 8 channels.
// Double-buffered smem input tile + per-cin weight slice; next-cin global
// loads prefetched into registers BEFORE the FFMA block (latency hidden).
// Inner loop: 9 input LDS (vectorized) + 18 LDS.128 weight broadcasts +
// 288 FFMA per cin  ->  FFMA-pipe bound.
// ---------------------------------------------------------------------------
template<int CIN, int OUTC, int STRIDE, bool TOKEN_OUT>
__global__ void __launch_bounds__(256) convfast(
    const float* __restrict__ in, const float* __restrict__ wgt,
    const float* __restrict__ bias, float* __restrict__ out,
    int Hin, int Win, int Ho, int Wo)
{
    constexpr int COG  = 8;
    constexpr int ITX  = 31*STRIDE + 3;          // 65 (s2) / 34 (s1)
    constexpr int ITY  = 31*STRIDE + 3;
    constexpr int ROWP = (ITX + 3) & ~3;         // 68 / 36
    constexpr int ELEMS = ITY * ITX;
    constexpr int NIT  = (ELEMS + 255) / 256;    // 17 / 5
    constexpr int NIV  = 3*STRIDE + 3;           // 9 / 6

    __shared__ float sIn[2][ITY*ROWP];
    __shared__ float sW[2][COG*9 + 8];

    const int tid = threadIdx.x;
    const int tx = tid & 7, ty = tid >> 3;
    const int groups = OUTC / COG;
    const int b = blockIdx.z / groups;
    const int cbase = (blockIdx.z % groups) * COG;
    const int X0 = blockIdx.x * 32, Y0 = blockIdx.y * 32;
    const int iy0 = Y0*STRIDE - 1, ix0 = X0*STRIDE - 1;
    const size_t HW = (size_t)Hin * Win;
    const float* inb = in + (size_t)b * CIN * HW;

    // staging coordinates precomputed once (no per-cin div/mod)
    int goff[NIT], soff[NIT];
#pragma unroll
    for (int it = 0; it < NIT; it++) {
        int idx = it*256 + tid;
        if (idx < ELEMS) {
            int r = idx / ITX, c = idx - r*ITX;
            int ih = iy0 + r, iw = ix0 + c;
            soff[it] = r*ROWP + c;
            goff[it] = ((unsigned)ih < (unsigned)Hin && (unsigned)iw < (unsigned)Win)
                       ? (ih*Win + iw) : -1;
        } else { soff[it] = -1; goff[it] = -1; }
    }
    const int wc = tid / 9, wtap = tid - wc*9;   // weight stage slot (tid<72)

    // stage cin 0
    {
#pragma unroll
        for (int it = 0; it < NIT; it++)
            if (soff[it] >= 0)
                sIn[0][soff[it]] = (goff[it] >= 0) ? __ldg(inb + goff[it]) : 0.f;
        if (tid < COG*9)
            sW[0][wtap*COG + wc] = __ldg(wgt + ((size_t)(cbase+wc)*CIN)*9 + wtap);
    }
    __syncthreads();

    float acc[4][COG];
#pragma unroll
    for (int j = 0; j < 4; j++)
#pragma unroll
        for (int c = 0; c < COG; c++) acc[j][c] = 0.f;

    for (int cin = 0; cin < CIN; cin++) {
        const int cur = cin & 1;

        // -------- prefetch next channel into registers (LDG issued early)
        float pin[NIT]; float pw = 0.f;
        if (cin + 1 < CIN) {
            const float* ic = inb + (size_t)(cin+1)*HW;
#pragma unroll
            for (int it = 0; it < NIT; it++)
                pin[it] = (soff[it] >= 0 && goff[it] >= 0) ? __ldg(ic + goff[it]) : 0.f;
            if (tid < COG*9)
                pw = __ldg(wgt + ((size_t)(cbase+wc)*CIN + cin + 1)*9 + wtap);
        }

        // -------- compute (hides the prefetch latency)
        const float* sc  = sIn[cur];
        const float* swc = sW[cur];
#pragma unroll
        for (int dy = 0; dy < 3; dy++) {
            const float* rp = sc + (ty*STRIDE + dy)*ROWP + tx*4*STRIDE;
            float iv[NIV];
            float4 A = *(const float4*)rp;
            iv[0]=A.x; iv[1]=A.y; iv[2]=A.z; iv[3]=A.w;
            if (STRIDE == 1) {
                float2 Bv = *(const float2*)(rp + 4);
                iv[4]=Bv.x; iv[5]=Bv.y;
            } else {
                float4 Bv = *(const float4*)(rp + 4);
                iv[4]=Bv.x; iv[5]=Bv.y; iv[6]=Bv.z; iv[7]=Bv.w;
                iv[8]=rp[8];
            }
#pragma unroll
            for (int dx = 0; dx < 3; dx++) {
                float4 w0 = *(const float4*)(swc + (dy*3+dx)*COG);
                float4 w1 = *(const float4*)(swc + (dy*3+dx)*COG + 4);
#pragma unroll
                for (int j = 0; j < 4; j++) {
                    float v = iv[j*STRIDE + dx];
                    acc[j][0] += v*w0.x; acc[j][1] += v*w0.y;
                    acc[j][2] += v*w0.z; acc[j][3] += v*w0.w;
                    acc[j][4] += v*w1.x; acc[j][5] += v*w1.y;
                    acc[j][6] += v*w1.z; acc[j][7] += v*w1.w;
                }
            }
        }

        // -------- commit prefetched data to the other buffer
        if (cin + 1 < CIN) {
            const int nxt = cur ^ 1;
#pragma unroll
            for (int it = 0; it < NIT; it++)
                if (soff[it] >= 0) sIn[nxt][soff[it]] = pin[it];
            if (tid < COG*9) sW[nxt][wtap*COG + wc] = pw;
        }
        __syncthreads();
    }

    // -------- epilogue: bias + SiLU + vectorized stores
    float bv[COG];
#pragma unroll
    for (int c = 0; c < COG; c++) bv[c] = __ldg(bias + cbase + c);

    const int oy = Y0 + ty;
    if (TOKEN_OUT) {
#pragma unroll
        for (int j = 0; j < 4; j++) {
            float vv[COG];
#pragma unroll
            for (int c = 0; c < COG; c++) {
                float v = acc[j][c] + bv[c];
                vv[c] = v / (1.f + __expf(-v));
            }
            size_t t = ((size_t)b*Ho + oy)*Wo + X0 + tx*4 + j;
            float4* op = (float4*)(out + t*OUTC + cbase);
            op[0] = make_float4(vv[0], vv[1], vv[2], vv[3]);
            op[1] = make_float4(vv[4], vv[5], vv[6], vv[7]);
        }
    } else {
#pragma unroll
        for (int c = 0; c < COG; c++) {
            float4 o;
            float* po = (float*)&o;
#pragma unroll
            for (int j = 0; j < 4; j++) {
                float v = acc[j][c] + bv[c];
                po[j] = v / (1.f + __expf(-v));
            }
            *(float4*)(out + (((size_t)b*OUTC + cbase + c)*Ho + oy)*Wo + X0 + tx*4) = o;
        }
    }
}

// ---------------------------------------------------------------------------
// Legacy conv (used only for the tiny 3->3 decoder conv)
// ---------------------------------------------------------------------------
template<int CIN, int OUTC, int COG, int STRIDE, bool TOKEN_OUT>
__global__ void __launch_bounds__(256) conv3x3(
    const float* __restrict__ in, const float* __restrict__ wgt,
    const float* __restrict__ bias, float* __restrict__ out,
    int Hin, int Win, int Ho, int Wo)
{
    constexpr int ITD = 15*STRIDE + 3;
    __shared__ float sW[COG*CIN*9];
    __shared__ float sIn[ITD*ITD];

    const int tid = threadIdx.x;
    const int groups = OUTC / COG;
    const int b  = blockIdx.z / groups;
    const int cg = blockIdx.z % groups;
    const int cbase = cg * COG;

    for (int i = tid; i < COG*CIN*9; i += 256)
        sW[i] = wgt[(size_t)cbase*CIN*9 + i];

    const int ty = tid >> 4, tx = tid & 15;
    const int oy = blockIdx.y*16 + ty;
    const int ox = blockIdx.x*16 + tx;

    float acc[COG];
#pragma unroll
    for (int c = 0; c < COG; c++) acc[c] = 0.f;

    const float* inb = in + (size_t)b * CIN * Hin * Win;
    const int iy0 = blockIdx.y*16*STRIDE - 1;
    const int ix0 = blockIdx.x*16*STRIDE - 1;
    const int base = (ty*STRIDE)*ITD + tx*STRIDE;

    for (int cin = 0; cin < CIN; cin++) {
        __syncthreads();
        const float* ic = inb + (size_t)cin * Hin * Win;
        for (int i = tid; i < ITD*ITD; i += 256) {
            int r = i / ITD, cc = i - r*ITD;
            int ih = iy0 + r, iw = ix0 + cc;
            float v = 0.f;
            if ((unsigned)ih < (unsigned)Hin && (unsigned)iw < (unsigned)Win)
                v = ic[ih*Win + iw];
            sIn[i] = v;
        }
        __syncthreads();
        const float* wp = sW + cin*9;
#pragma unroll
        for (int dy = 0; dy < 3; dy++)
#pragma unroll
            for (int dx = 0; dx < 3; dx++) {
                float iv = sIn[base + dy*ITD + dx];
#pragma unroll
                for (int c = 0; c < COG; c++)
                    acc[c] += iv * wp[c*CIN*9 + dy*3 + dx];
            }
    }

#pragma unroll
    for (int c = 0; c < COG; c++) {
        float v = acc[c] + bias[cbase + c];
        v = v / (1.f + __expf(-v));
        if (TOKEN_OUT) {
            size_t t = ((size_t)b*Ho + oy)*Wo + ox;
            out[t*OUTC + cbase + c] = v;
        } else {
            out[(((size_t)b*OUTC + cbase + c)*Ho + oy)*Wo + ox] = v;
        }
    }
}

// ---------------------------------------------------------------------------
// Memcell pass 1: w = softmax(z @ K^T / 4) per token.
// ---------------------------------------------------------------------------
__global__ void __launch_bounds__(256) memcell_softmax(
    const float* __restrict__ z, const float* __restrict__ ck,
    float* __restrict__ wout)
{
    __shared__ float sK[Mm*Nn];
    const int tid = threadIdx.x;
    for (int i = tid; i < Mm*Nn; i += 256) sK[i] = ck[i];
    __syncthreads();

    const int t = blockIdx.x*256 + tid;
    const float4* zp = (const float4*)(z + (size_t)t*Nn);
    float4 z0 = zp[0], z1 = zp[1], z2 = zp[2], z3 = zp[3];

    float s[Mm];
    float mx = -1e30f;
#pragma unroll
    for (int m = 0; m < Mm; m++) {
        const float* k = sK + m*Nn;
        float d = z0.x*k[0] + z0.y*k[1] + z0.z*k[2] + z0.w*k[3]
                + z1.x*k[4] + z1.y*k[5] + z1.z*k[6] + z1.w*k[7]
                + z2.x*k[8] + z2.y*k[9] + z2.z*k[10]+ z2.w*k[11]
                + z3.x*k[12]+ z3.y*k[13]+ z3.z*k[14]+ z3.w*k[15];
        d *= 0.25f;
        s[m] = d;
        mx = fmaxf(mx, d);
    }
    float sum = 0.f;
#pragma unroll
    for (int m = 0; m < Mm; m++) { s[m] = __expf(s[m]-mx); sum += s[m]; }
    float inv = 1.f / sum;
    float4* wo = (float4*)(wout + (size_t)t*Mm);
#pragma unroll
    for (int j = 0; j < Mm/4; j++) {
        float4 v; v.x = s[4*j]*inv; v.y = s[4*j+1]*inv;
        v.z = s[4*j+2]*inv; v.w = s[4*j+3]*inv;
        wo[j] = v;
    }
}

// ---------------------------------------------------------------------------
// Memcell pass 2: block partials of [G | U], G = W^T W, U = W^T t_star.
// ---------------------------------------------------------------------------
__global__ void __launch_bounds__(256) memcell_outer(
    const float* __restrict__ wmat, const float* __restrict__ ts,
    float* __restrict__ part)
{
    __shared__ float sv[8*160];
    const int tid = threadIdx.x;
    const int ti = tid >> 5;
    const int tj = tid & 31;
    float acc[4][5];
#pragma unroll
    for (int a = 0; a < 4; a++)
#pragma unroll
        for (int q = 0; q < 5; q++) acc[a][q] = 0.f;

    const int tokb = blockIdx.x * 128;
    for (int ch = 0; ch < 128; ch += 8) {
        __syncthreads();
#pragma unroll
        for (int l = 0; l < 5; l++) {
            int idx = l*256 + tid;
            int tk = idx / 160, f = idx - tk*160;
            int t = tokb + ch + tk;
            sv[tk*160 + f] = (f < 32) ? wmat[(size_t)t*32 + f]
                                      : ts[(size_t)t*128 + (f-32)];
        }
        __syncthreads();
#pragma unroll
        for (int tk = 0; tk < 8; tk++) {
            float wi[4], vj[5];
#pragma unroll
            for (int a = 0; a < 4; a++) wi[a] = sv[tk*160 + ti*4 + a];
#pragma unroll
            for (int q = 0; q < 5; q++) vj[q] = sv[tk*160 + tj*5 + q];
#pragma unroll
            for (int a = 0; a < 4; a++)
#pragma unroll
                for (int q = 0; q < 5; q++) acc[a][q] += wi[a]*vj[q];
        }
    }
    float* pp = part + (size_t)blockIdx.x * 5120;
#pragma unroll
    for (int a = 0; a < 4; a++)
#pragma unroll
        for (int q = 0; q < 5; q++)
            pp[(ti*4+a)*160 + tj*5 + q] = acc[a][q];
}

__global__ void __launch_bounds__(256) reduce_partials(
    const float* __restrict__ part, float* __restrict__ gu)
{
    int cell = blockIdx.x*256 + threadIdx.x;
    float s = 0.f;
#pragma unroll 8
    for (int p = 0; p < 1024; p++) s += part[(size_t)p*5120 + cell];
    gu[cell] = s;
}

__global__ void __launch_bounds__(256) cell_update(
    const float* __restrict__ gu, const float* __restrict__ cv,
    float* __restrict__ vnew)
{
    __shared__ float sG[Mm*Mm];
    __shared__ float sV[Mm*Ss];
    const int tid = threadIdx.x;
    for (int i = tid; i < Mm*Mm; i += 256) {
        int m = i >> 5, j = i & 31;
        sG[i] = gu[m*160 + j];
    }
    for (int i = tid; i < Mm*Ss; i += 256) sV[i] = cv[i];
    __syncthreads();
    for (int k = 0; k < 16; k++) {
        int cell = k*256 + tid;
        int m = cell >> 7, s0 = cell & 127;
        float d = gu[m*160 + 32 + s0];
#pragma unroll
        for (int mp = 0; mp < Mm; mp++) d -= sG[m*32 + mp] * sV[mp*128 + s0];
        vnew[cell] = sV[cell] + ALPHA * d;
    }
}

// ---------------------------------------------------------------------------
// Memcell pass 3: t_read = W @ cell_v_new -> NCHW [B,S,H2,W2].
// ---------------------------------------------------------------------------
__global__ void __launch_bounds__(256) memcell_read(
    const float* __restrict__ wmat, const float* __restrict__ vnew,
    float* __restrict__ d0m)
{
    __shared__ float sV[Mm*Ss];
    __shared__ float sW[64*33];
    const int tid = threadIdx.x;
    for (int i = tid; i < Mm*Ss; i += 256) sV[i] = vnew[i];
    const int tbase = blockIdx.x * 64;
    for (int i = tid; i < 64*32; i += 256) {
        int tk = i >> 5, m = i & 31;
        sW[tk*33 + m] = wmat[(size_t)(tbase + tk)*32 + m];
    }
    __syncthreads();

    const int lane = tid & 31, wid = tid >> 5;
    const int cb = wid * 16;
    float a0[16], a1[16];
#pragma unroll
    for (int c = 0; c < 16; c++) { a0[c] = 0.f; a1[c] = 0.f; }

    const float* w0 = sW + lane*33;
    const float* w1 = sW + (lane + 32)*33;
#pragma unroll 4
    for (int m = 0; m < Mm; m++) {
        float x0 = w0[m], x1 = w1[m];
        const float4* vv = (const float4*)(sV + m*128 + cb);
#pragma unroll
        for (int q = 0; q < 4; q++) {
            float4 v = vv[q];
            a0[q*4+0] += x0*v.x; a0[q*4+1] += x0*v.y;
            a0[q*4+2] += x0*v.z; a0[q*4+3] += x0*v.w;
            a1[q*4+0] += x1*v.x; a1[q*4+1] += x1*v.y;
            a1[q*4+2] += x1*v.z; a1[q*4+3] += x1*v.w;
        }
    }
    const int b = tbase >> 14;
    const int rem = tbase & 16383;
    const int h = rem >> 7;
    const int wcp = rem & 127;
    size_t obase = ((size_t)b*Ss)*((size_t)H2*W2) + (size_t)h*W2 + wcp;
#pragma unroll
    for (int c = 0; c < 16; c++) {
        size_t o = obase + (size_t)(cb + c)*(H2*W2);
        d0m[o + lane]      = a0[c];
        d0m[o + 32 + lane] = a1[c];
    }
}

// ---------------------------------------------------------------------------
// ConvTranspose2d(128->3, k4, s2, p1) + bias + SiLU.
// Weights reorganized per output-parity so each thread's 12 live weights are
// 3 contiguous float4 in smem. 16-cin chunks halve barrier count.
// ---------------------------------------------------------------------------
__global__ void __launch_bounds__(256) deconv_kernel(
    const float* __restrict__ in, const float* __restrict__ dw,
    const float* __restrict__ db, float* __restrict__ out)
{
    __shared__ float sWd[4*128*12];              // [parity][cin][o][k] 24.6 KB
    __shared__ float sIn[16*100];                // 16 cins x 10x10
    const int tid = threadIdx.x;
    for (int i = tid; i < 4*128*12; i += 256) {
        int p = i / 1536, rem = i - p*1536;
        int cin = rem / 12, rr = rem - cin*12;
        int o = rr >> 2, k = rr & 3;
        int py = p >> 1, px = p & 1;
        int ky = py + 2*(k >> 1), kx = px + 2*(k & 1);
        sWd[i] = dw[cin*48 + o*16 + ky*4 + kx];
    }

    const int b  = blockIdx.z;
    const int Y0 = blockIdx.y*16, X0 = blockIdx.x*16;
    const int ty = tid >> 4, tx = tid & 15;
    const int y = Y0 + ty, x = X0 + tx;
    const int hb = (Y0 >> 1) - 1, wb = (X0 >> 1) - 1;

    const int py = (y + 1) & 1, px = (x + 1) & 1;
    const int hs0 = ((y + 1 - py) >> 1) - hb;
    const int ws0 = ((x + 1 - px) >> 1) - wb;

    const float* wp = sWd + (py*2 + px)*1536;
    float acc[3] = {0.f, 0.f, 0.f};
    const float* inb = in + (size_t)b * Ss * H2 * W2;

    for (int c0 = 0; c0 < Ss; c0 += 16) {
        __syncthreads();
        for (int i = tid; i < 1600; i += 256) {
            int c = i / 100, rr = i - c*100;
            int r = rr / 10, cc = rr - r*10;
            int h = hb + r, w = wb + cc;
            float v = 0.f;
            if ((unsigned)h < (unsigned)H2 && (unsigned)w < (unsigned)W2)
                v = inb[((size_t)(c0 + c)*H2 + h)*W2 + w];
            sIn[i] = v;
        }
        __syncthreads();
#pragma unroll
        for (int c = 0; c < 16; c++) {
            const float* sc = sIn + c*100;
            float i00 = sc[hs0*10 + ws0];
            float i01 = sc[hs0*10 + ws0 - 1];
            float i10 = sc[(hs0-1)*10 + ws0];
            float i11 = sc[(hs0-1)*10 + ws0 - 1];
            const float4* w4 = (const float4*)(wp + (c0 + c)*12);
#pragma unroll
            for (int o = 0; o < 3; o++) {
                float4 w = w4[o];
                acc[o] += i00*w.x + i01*w.y + i10*w.z + i11*w.w;
            }
        }
    }
#pragma unroll
    for (int o = 0; o < 3; o++) {
        float v = acc[o] + db[o];
        v = v / (1.f + __expf(-v));
        out[(((size_t)b*3 + o)*HIN + y)*WIN + x] = v;
    }
}

// ---------------------------------------------------------------------------
// Launch sequence
// ---------------------------------------------------------------------------
extern "C" void kernel_launch(void* const* d_in, const int* in_sizes, int n_in,
                              void* d_out, int out_size)
{
    const float* x      = (const float*)d_in[0];
    const float* e0n_w1 = (const float*)d_in[1];
    const float* e0n_b1 = (const float*)d_in[2];
    const float* e0n_w2 = (const float*)d_in[3];
    const float* e0n_b2 = (const float*)d_in[4];
    const float* e0s_w1 = (const float*)d_in[5];
    const float* e0s_b1 = (const float*)d_in[6];
    const float* e0s_w2 = (const float*)d_in[7];
    const float* e0s_b2 = (const float*)d_in[8];
    const float* d0_dw  = (const float*)d_in[9];
    const float* d0_db  = (const float*)d_in[10];
    const float* d0_cw  = (const float*)d_in[11];
    const float* d0_cb  = (const float*)d_in[12];
    const float* cell_k = (const float*)d_in[13];
    const float* cell_v = (const float*)d_in[14];
    float* outp = (float*)d_out;

    void *p_a1n, *p_a1s, *p_z, *p_ts, *p_w, *p_part, *p_gu, *p_vnew, *p_d0m, *p_dec;
    cudaGetSymbolAddress(&p_a1n, g_a1n);
    cudaGetSymbolAddress(&p_a1s, g_a1s);
    cudaGetSymbolAddress(&p_z,   g_z);
    cudaGetSymbolAddress(&p_ts,  g_ts);
    cudaGetSymbolAddress(&p_w,   g_w);
    cudaGetSymbolAddress(&p_part,g_part);
    cudaGetSymbolAddress(&p_gu,  g_gu);
    cudaGetSymbolAddress(&p_vnew,g_vnew);
    cudaGetSymbolAddress(&p_d0m, g_d0m);
    cudaGetSymbolAddress(&p_dec, g_dec);

    // Encoders (all via the register-blocked FFMA-bound conv)
    convfast<3,16,1,false><<<dim3(8,8,Bb*2),256>>>(
        x, e0n_w1, e0n_b1, (float*)p_a1n, HIN, WIN, HIN, WIN);
    convfast<3,128,1,false><<<dim3(8,8,Bb*16),256>>>(
        x, e0s_w1, e0s_b1, (float*)p_a1s, HIN, WIN, HIN, WIN);
    convfast<16,16,2,true><<<dim3(4,4,Bb*2),256>>>(
        (const float*)p_a1n, e0n_w2, e0n_b2, (float*)p_z, HIN, WIN, H2, W2);
    convfast<128,128,2,true><<<dim3(4,4,Bb*16),256>>>(
        (const float*)p_a1s, e0s_w2, e0s_b2, (float*)p_ts, HIN, WIN, H2, W2);

    // Memcell
    memcell_softmax<<<Tt/256,256>>>((const float*)p_z, cell_k, (float*)p_w);
    memcell_outer<<<1024,256>>>((const float*)p_w, (const float*)p_ts, (float*)p_part);
    reduce_partials<<<20,256>>>((const float*)p_part, (float*)p_gu);
    cell_update<<<1,256>>>((const float*)p_gu, cell_v, (float*)p_vnew);
    memcell_read<<<Tt/64,256>>>((const float*)p_w, (const float*)p_vnew, (float*)p_d0m);

    // Decoder
    deconv_kernel<<<dim3(16,16,Bb),256>>>(
        (const float*)p_d0m, d0_dw, d0_db, (float*)p_dec);
    conv3x3<3,3,3,1,false><<<dim3(16,16,Bb),256>>>(
        (const float*)p_dec, d0_cw, d0_cb, outp, HIN, WIN, HIN, WIN);
}

// round 4
// speedup vs baseline: 2.1207x; 1.0355x over previous
#include <cuda_runtime.h>
#include <cuda_bf16.h>
#include <cstdint>

// ---------------------------------------------------------------------------
// Problem constants
// ---------------------------------------------------------------------------
#define Bb   8
#define HIN  256
#define WIN  256
#define H2   128
#define W2   128
#define Nn   16
#define Mm   32
#define Ss   128
#define Tt   (Bb*H2*W2)          // 131072 tokens
#define ALPHA 1e-6f

// ---------------------------------------------------------------------------
// Scratch buffers (static device globals; no cudaMalloc allowed)
// ---------------------------------------------------------------------------
__device__ float g_a1n [Bb*Nn*HIN*WIN];
__device__ float g_a1s [(size_t)Bb*Ss*HIN*WIN];
__device__ float g_z   [(size_t)Tt*Nn];
__device__ float g_ts  [(size_t)Tt*Ss];
__device__ float g_w   [(size_t)Tt*Mm];
__device__ float g_part[(size_t)1024*32*160];
__device__ float g_gu  [32*160];
__device__ float g_vnew[Mm*Ss];
__device__ float g_d0m [(size_t)Bb*Ss*H2*W2];
__device__ float g_dec [(size_t)Bb*3*HIN*WIN];

// ---------------------------------------------------------------------------
// cp.async helpers
// ---------------------------------------------------------------------------
__device__ __forceinline__ void cp_async4(unsigned dst, const float* src, int sz) {
    asm volatile("cp.async.ca.shared.global [%0], [%1], 4, %2;\n"
                 :: "r"(dst), "l"(src), "r"(sz));
}
__device__ __forceinline__ void cp_async4u(unsigned dst, const float* src) {
    asm volatile("cp.async.ca.shared.global [%0], [%1], 4;\n"
                 :: "r"(dst), "l"(src));
}
__device__ __forceinline__ void cp_commit() {
    asm volatile("cp.async.commit_group;\n" ::: "memory");
}
__device__ __forceinline__ void cp_wait0() {
    asm volatile("cp.async.wait_group 0;\n" ::: "memory");
}

// ---------------------------------------------------------------------------
// Fast fused conv3x3 + bias + SiLU.  pad=1, stride in {1,2}.
// 256 threads -> 32x32 output tile; thread = 4 x-pixels x 8 channels.
// STRIDE=2: input tile stored parity-split (even/odd columns in separate
// planes) so all tap loads are lane-contiguous LDS.128 -> L1 wavefronts
// halved vs strided access. Staging via cp.async (zfill OOB), incremental
// address generation (no per-thread offset arrays), double buffered.
// ---------------------------------------------------------------------------
template<int CIN, int OUTC, int STRIDE, bool TOKEN_OUT>
__global__ void __launch_bounds__(256) convfast(
    const float* __restrict__ in, const float* __restrict__ wgt,
    const float* __restrict__ bias, float* __restrict__ out,
    int Hin, int Win, int Ho, int Wo)
{
    constexpr int COG  = 8;
    constexpr int ITX  = 31*STRIDE + 3;          // 65 (s2) / 34 (s1)
    constexpr int ITY  = ITX;
    constexpr int ODD  = 36;                     // odd-plane float offset (s2)
    constexpr int SRS  = (STRIDE==2) ? 72 : 36;  // smem row stride (floats)
    constexpr int ELEMS = ITY * ITX;             // 4225 / 1156
    constexpr int NIT  = (ELEMS + 255) / 256;    // 17 / 5
    constexpr int TAIL = ELEMS - (NIT-1)*256;    // 129 / 132
    constexpr int STEP_R = 256 / ITX;            // 3 / 7
    constexpr int STEP_C = 256 - STEP_R*ITX;     // 61 / 18

    __shared__ float sIn[2][ITY*SRS];
    __shared__ float sW[2][COG*9 + 8];

    const int tid = threadIdx.x;
    const int tx = tid & 7, ty = tid >> 3;
    const int groups = OUTC / COG;
    const int b = blockIdx.z / groups;
    const int cbase = (blockIdx.z % groups) * COG;
    const int X0 = blockIdx.x * 32, Y0 = blockIdx.y * 32;
    const int iy0 = Y0*STRIDE - 1, ix0 = X0*STRIDE - 1;
    const size_t HW = (size_t)Hin * Win;
    const float* inb = in + (size_t)b * CIN * HW;

    const int r0 = tid / ITX;
    const int c0 = tid - r0*ITX;
    const int wc = tid / 9, wtap = tid - wc*9;   // weight stage slot (tid<72)

    // ---- staging (cp.async into buffer `buf` for channel `cin`)
    auto stage = [&](int buf, int cin) {
        const float* ic = inb + (size_t)cin * HW;
        unsigned sbase = (unsigned)__cvta_generic_to_shared(&sIn[buf][0]);
        int r = r0, c = c0;
#pragma unroll
        for (int it = 0; it < NIT; it++) {
            if (it < NIT-1 || tid < TAIL) {
                int ih = iy0 + r, iw = ix0 + c;
                bool ok = ((unsigned)ih < (unsigned)Hin) &
                          ((unsigned)iw < (unsigned)Win);
                int sof;
                if (STRIDE == 2) sof = r*SRS + ((c & 1) ? ODD : 0) + (c >> 1);
                else             sof = r*SRS + c;
                const float* src = ic + (ok ? ((size_t)ih*Win + iw) : 0);
                cp_async4(sbase + sof*4, src, ok ? 4 : 0);
            }
            r += STEP_R; c += STEP_C;
            if (c >= ITX) { c -= ITX; r++; }
        }
        if (tid < COG*9) {
            unsigned dst = (unsigned)__cvta_generic_to_shared(
                               &sW[buf][wtap*COG + wc]);
            cp_async4u(dst, wgt + ((size_t)(cbase+wc)*CIN + cin)*9 + wtap);
        }
    };

    stage(0, 0);
    cp_commit();
    cp_wait0();
    __syncthreads();

    float acc[4][COG];
#pragma unroll
    for (int j = 0; j < 4; j++)
#pragma unroll
        for (int c = 0; c < COG; c++) acc[j][c] = 0.f;

    for (int cin = 0; cin < CIN; cin++) {
        const int cur = cin & 1;
        if (cin + 1 < CIN) { stage(cur^1, cin+1); cp_commit(); }

        const float* sc  = sIn[cur];
        const float* swp = sW[cur];
#pragma unroll
        for (int dy = 0; dy < 3; dy++) {
            float V[3][4];
            if (STRIDE == 2) {
                const float* rp = sc + (ty*2 + dy)*SRS;
                float4 E = *(const float4*)(rp + tx*4);
                float  e4 = rp[tx*4 + 4];
                float4 O = *(const float4*)(rp + ODD + tx*4);
                V[0][0]=E.x; V[0][1]=E.y; V[0][2]=E.z; V[0][3]=E.w;
                V[1][0]=O.x; V[1][1]=O.y; V[1][2]=O.z; V[1][3]=O.w;
                V[2][0]=E.y; V[2][1]=E.z; V[2][2]=E.w; V[2][3]=e4;
            } else {
                const float* rp = sc + (ty + dy)*SRS + tx*4;
                float4 A = *(const float4*)rp;
                float2 Bv = *(const float2*)(rp + 4);
                float iv6[6] = {A.x, A.y, A.z, A.w, Bv.x, Bv.y};
#pragma unroll
                for (int dx = 0; dx < 3; dx++)
#pragma unroll
                    for (int k = 0; k < 4; k++) V[dx][k] = iv6[k+dx];
            }
#pragma unroll
            for (int dx = 0; dx < 3; dx++) {
                float4 w0 = *(const float4*)(swp + (dy*3+dx)*COG);
                float4 w1 = *(const float4*)(swp + (dy*3+dx)*COG + 4);
#pragma unroll
                for (int j = 0; j < 4; j++) {
                    float v = V[dx][j];
                    acc[j][0] += v*w0.x; acc[j][1] += v*w0.y;
                    acc[j][2] += v*w0.z; acc[j][3] += v*w0.w;
                    acc[j][4] += v*w1.x; acc[j][5] += v*w1.y;
                    acc[j][6] += v*w1.z; acc[j][7] += v*w1.w;
                }
            }
        }
        if (cin + 1 < CIN) cp_wait0();
        __syncthreads();
    }

    // -------- epilogue: bias + SiLU + vectorized stores
    float bv[COG];
#pragma unroll
    for (int c = 0; c < COG; c++) bv[c] = __ldg(bias + cbase + c);

    const int oy = Y0 + ty;
    if (TOKEN_OUT) {
#pragma unroll
        for (int j = 0; j < 4; j++) {
            float vv[COG];
#pragma unroll
            for (int c = 0; c < COG; c++) {
                float v = acc[j][c] + bv[c];
                vv[c] = v / (1.f + __expf(-v));
            }
            size_t t = ((size_t)b*Ho + oy)*Wo + X0 + tx*4 + j;
            float4* op = (float4*)(out + t*OUTC + cbase);
            op[0] = make_float4(vv[0], vv[1], vv[2], vv[3]);
            op[1] = make_float4(vv[4], vv[5], vv[6], vv[7]);
        }
    } else {
#pragma unroll
        for (int c = 0; c < COG; c++) {
            float4 o;
            float* po = (float*)&o;
#pragma unroll
            for (int j = 0; j < 4; j++) {
                float v = acc[j][c] + bv[c];
                po[j] = v / (1.f + __expf(-v));
            }
            *(float4*)(out + (((size_t)b*OUTC + cbase + c)*Ho + oy)*Wo + X0 + tx*4) = o;
        }
    }
}

// ---------------------------------------------------------------------------
// Legacy conv (used only for the tiny 3->3 decoder conv)
// ---------------------------------------------------------------------------
template<int CIN, int OUTC, int COG, int STRIDE, bool TOKEN_OUT>
__global__ void __launch_bounds__(256) conv3x3(
    const float* __restrict__ in, const float* __restrict__ wgt,
    const float* __restrict__ bias, float* __restrict__ out,
    int Hin, int Win, int Ho, int Wo)
{
    constexpr int ITD = 15*STRIDE + 3;
    __shared__ float sW[COG*CIN*9];
    __shared__ float sIn[ITD*ITD];

    const int tid = threadIdx.x;
    const int groups = OUTC / COG;
    const int b  = blockIdx.z / groups;
    const int cg = blockIdx.z % groups;
    const int cbase = cg * COG;

    for (int i = tid; i < COG*CIN*9; i += 256)
        sW[i] = wgt[(size_t)cbase*CIN*9 + i];

    const int ty = tid >> 4, tx = tid & 15;
    const int oy = blockIdx.y*16 + ty;
    const int ox = blockIdx.x*16 + tx;

    float acc[COG];
#pragma unroll
    for (int c = 0; c < COG; c++) acc[c] = 0.f;

    const float* inb = in + (size_t)b * CIN * Hin * Win;
    const int iy0 = blockIdx.y*16*STRIDE - 1;
    const int ix0 = blockIdx.x*16*STRIDE - 1;
    const int base = (ty*STRIDE)*ITD + tx*STRIDE;

    for (int cin = 0; cin < CIN; cin++) {
        __syncthreads();
        const float* ic = inb + (size_t)cin * Hin * Win;
        for (int i = tid; i < ITD*ITD; i += 256) {
            int r = i / ITD, cc = i - r*ITD;
            int ih = iy0 + r, iw = ix0 + cc;
            float v = 0.f;
            if ((unsigned)ih < (unsigned)Hin && (unsigned)iw < (unsigned)Win)
                v = ic[ih*Win + iw];
            sIn[i] = v;
        }
        __syncthreads();
        const float* wp = sW + cin*9;
#pragma unroll
        for (int dy = 0; dy < 3; dy++)
#pragma unroll
            for (int dx = 0; dx < 3; dx++) {
                float iv = sIn[base + dy*ITD + dx];
#pragma unroll
                for (int c = 0; c < COG; c++)
                    acc[c] += iv * wp[c*CIN*9 + dy*3 + dx];
            }
    }

#pragma unroll
    for (int c = 0; c < COG; c++) {
        float v = acc[c] + bias[cbase + c];
        v = v / (1.f + __expf(-v));
        if (TOKEN_OUT) {
            size_t t = ((size_t)b*Ho + oy)*Wo + ox;
            out[t*OUTC + cbase + c] = v;
        } else {
            out[(((size_t)b*OUTC + cbase + c)*Ho + oy)*Wo + ox] = v;
        }
    }
}

// ---------------------------------------------------------------------------
// Memcell pass 1: w = softmax(z @ K^T / 4) per token.
// ---------------------------------------------------------------------------
__global__ void __launch_bounds__(256) memcell_softmax(
    const float* __restrict__ z, const float* __restrict__ ck,
    float* __restrict__ wout)
{
    __shared__ float sK[Mm*Nn];
    const int tid = threadIdx.x;
    for (int i = tid; i < Mm*Nn; i += 256) sK[i] = ck[i];
    __syncthreads();

    const int t = blockIdx.x*256 + tid;
    const float4* zp = (const float4*)(z + (size_t)t*Nn);
    float4 z0 = zp[0], z1 = zp[1], z2 = zp[2], z3 = zp[3];

    float s[Mm];
    float mx = -1e30f;
#pragma unroll
    for (int m = 0; m < Mm; m++) {
        const float* k = sK + m*Nn;
        float d = z0.x*k[0] + z0.y*k[1] + z0.z*k[2] + z0.w*k[3]
                + z1.x*k[4] + z1.y*k[5] + z1.z*k[6] + z1.w*k[7]
                + z2.x*k[8] + z2.y*k[9] + z2.z*k[10]+ z2.w*k[11]
                + z3.x*k[12]+ z3.y*k[13]+ z3.z*k[14]+ z3.w*k[15];
        d *= 0.25f;
        s[m] = d;
        mx = fmaxf(mx, d);
    }
    float sum = 0.f;
#pragma unroll
    for (int m = 0; m < Mm; m++) { s[m] = __expf(s[m]-mx); sum += s[m]; }
    float inv = 1.f / sum;
    float4* wo = (float4*)(wout + (size_t)t*Mm);
#pragma unroll
    for (int j = 0; j < Mm/4; j++) {
        float4 v; v.x = s[4*j]*inv; v.y = s[4*j+1]*inv;
        v.z = s[4*j+2]*inv; v.w = s[4*j+3]*inv;
        wo[j] = v;
    }
}

// ---------------------------------------------------------------------------
// Memcell pass 2: block partials of [G | U], G = W^T W, U = W^T t_star.
// ---------------------------------------------------------------------------
__global__ void __launch_bounds__(256) memcell_outer(
    const float* __restrict__ wmat, const float* __restrict__ ts,
    float* __restrict__ part)
{
    __shared__ float sv[8*160];
    const int tid = threadIdx.x;
    const int ti = tid >> 5;
    const int tj = tid & 31;
    float acc[4][5];
#pragma unroll
    for (int a = 0; a < 4; a++)
#pragma unroll
        for (int q = 0; q < 5; q++) acc[a][q] = 0.f;

    const int tokb = blockIdx.x * 128;
    for (int ch = 0; ch < 128; ch += 8) {
        __syncthreads();
#pragma unroll
        for (int l = 0; l < 5; l++) {
            int idx = l*256 + tid;
            int tk = idx / 160, f = idx - tk*160;
            int t = tokb + ch + tk;
            sv[tk*160 + f] = (f < 32) ? wmat[(size_t)t*32 + f]
                                      : ts[(size_t)t*128 + (f-32)];
        }
        __syncthreads();
#pragma unroll
        for (int tk = 0; tk < 8; tk++) {
            float wi[4], vj[5];
#pragma unroll
            for (int a = 0; a < 4; a++) wi[a] = sv[tk*160 + ti*4 + a];
#pragma unroll
            for (int q = 0; q < 5; q++) vj[q] = sv[tk*160 + tj*5 + q];
#pragma unroll
            for (int a = 0; a < 4; a++)
#pragma unroll
                for (int q = 0; q < 5; q++) acc[a][q] += wi[a]*vj[q];
        }
    }
    float* pp = part + (size_t)blockIdx.x * 5120;
#pragma unroll
    for (int a = 0; a < 4; a++)
#pragma unroll
        for (int q = 0; q < 5; q++)
            pp[(ti*4+a)*160 + tj*5 + q] = acc[a][q];
}

__global__ void __launch_bounds__(256) reduce_partials(
    const float* __restrict__ part, float* __restrict__ gu)
{
    int cell = blockIdx.x*256 + threadIdx.x;
    float s = 0.f;
#pragma unroll 8
    for (int p = 0; p < 1024; p++) s += part[(size_t)p*5120 + cell];
    gu[cell] = s;
}

__global__ void __launch_bounds__(256) cell_update(
    const float* __restrict__ gu, const float* __restrict__ cv,
    float* __restrict__ vnew)
{
    __shared__ float sG[Mm*Mm];
    __shared__ float sV[Mm*Ss];
    const int tid = threadIdx.x;
    for (int i = tid; i < Mm*Mm; i += 256) {
        int m = i >> 5, j = i & 31;
        sG[i] = gu[m*160 + j];
    }
    for (int i = tid; i < Mm*Ss; i += 256) sV[i] = cv[i];
    __syncthreads();
    for (int k = 0; k < 16; k++) {
        int cell = k*256 + tid;
        int m = cell >> 7, s0 = cell & 127;
        float d = gu[m*160 + 32 + s0];
#pragma unroll
        for (int mp = 0; mp < Mm; mp++) d -= sG[m*32 + mp] * sV[mp*128 + s0];
        vnew[cell] = sV[cell] + ALPHA * d;
    }
}

// ---------------------------------------------------------------------------
// Memcell pass 3: t_read = W @ cell_v_new -> NCHW [B,S,H2,W2].
// ---------------------------------------------------------------------------
__global__ void __launch_bounds__(256) memcell_read(
    const float* __restrict__ wmat, const float* __restrict__ vnew,
    float* __restrict__ d0m)
{
    __shared__ float sV[Mm*Ss];
    __shared__ float sW[64*33];
    const int tid = threadIdx.x;
    for (int i = tid; i < Mm*Ss; i += 256) sV[i] = vnew[i];
    const int tbase = blockIdx.x * 64;
    for (int i = tid; i < 64*32; i += 256) {
        int tk = i >> 5, m = i & 31;
        sW[tk*33 + m] = wmat[(size_t)(tbase + tk)*32 + m];
    }
    __syncthreads();

    const int lane = tid & 31, wid = tid >> 5;
    const int cb = wid * 16;
    float a0[16], a1[16];
#pragma unroll
    for (int c = 0; c < 16; c++) { a0[c] = 0.f; a1[c] = 0.f; }

    const float* w0 = sW + lane*33;
    const float* w1 = sW + (lane + 32)*33;
#pragma unroll 4
    for (int m = 0; m < Mm; m++) {
        float x0 = w0[m], x1 = w1[m];
        const float4* vv = (const float4*)(sV + m*128 + cb);
#pragma unroll
        for (int q = 0; q < 4; q++) {
            float4 v = vv[q];
            a0[q*4+0] += x0*v.x; a0[q*4+1] += x0*v.y;
            a0[q*4+2] += x0*v.z; a0[q*4+3] += x0*v.w;
            a1[q*4+0] += x1*v.x; a1[q*4+1] += x1*v.y;
            a1[q*4+2] += x1*v.z; a1[q*4+3] += x1*v.w;
        }
    }
    const int b = tbase >> 14;
    const int rem = tbase & 16383;
    const int h = rem >> 7;
    const int wcp = rem & 127;
    size_t obase = ((size_t)b*Ss)*((size_t)H2*W2) + (size_t)h*W2 + wcp;
#pragma unroll
    for (int c = 0; c < 16; c++) {
        size_t o = obase + (size_t)(cb + c)*(H2*W2);
        d0m[o + lane]      = a0[c];
        d0m[o + 32 + lane] = a1[c];
    }
}

// ---------------------------------------------------------------------------
// ConvTranspose2d(128->3, k4, s2, p1) + bias + SiLU.
// ---------------------------------------------------------------------------
__global__ void __launch_bounds__(256) deconv_kernel(
    const float* __restrict__ in, const float* __restrict__ dw,
    const float* __restrict__ db, float* __restrict__ out)
{
    __shared__ float sWd[4*128*12];              // [parity][cin][o][k] 24.6 KB
    __shared__ float sIn[16*100];                // 16 cins x 10x10
    const int tid = threadIdx.x;
    for (int i = tid; i < 4*128*12; i += 256) {
        int p = i / 1536, rem = i - p*1536;
        int cin = rem / 12, rr = rem - cin*12;
        int o = rr >> 2, k = rr & 3;
        int py = p >> 1, px = p & 1;
        int ky = py + 2*(k >> 1), kx = px + 2*(k & 1);
        sWd[i] = dw[cin*48 + o*16 + ky*4 + kx];
    }

    const int b  = blockIdx.z;
    const int Y0 = blockIdx.y*16, X0 = blockIdx.x*16;
    const int ty = tid >> 4, tx = tid & 15;
    const int y = Y0 + ty, x = X0 + tx;
    const int hb = (Y0 >> 1) - 1, wb = (X0 >> 1) - 1;

    const int py = (y + 1) & 1, px = (x + 1) & 1;
    const int hs0 = ((y + 1 - py) >> 1) - hb;
    const int ws0 = ((x + 1 - px) >> 1) - wb;

    const float* wp = sWd + (py*2 + px)*1536;
    float acc[3] = {0.f, 0.f, 0.f};
    const float* inb = in + (size_t)b * Ss * H2 * W2;

    for (int c0 = 0; c0 < Ss; c0 += 16) {
        __syncthreads();
        for (int i = tid; i < 1600; i += 256) {
            int c = i / 100, rr = i - c*100;
            int r = rr / 10, cc = rr - r*10;
            int h = hb + r, w = wb + cc;
            float v = 0.f;
            if ((unsigned)h < (unsigned)H2 && (unsigned)w < (unsigned)W2)
                v = inb[((size_t)(c0 + c)*H2 + h)*W2 + w];
            sIn[i] = v;
        }
        __syncthreads();
#pragma unroll
        for (int c = 0; c < 16; c++) {
            const float* sc = sIn + c*100;
            float i00 = sc[hs0*10 + ws0];
            float i01 = sc[hs0*10 + ws0 - 1];
            float i10 = sc[(hs0-1)*10 + ws0];
            float i11 = sc[(hs0-1)*10 + ws0 - 1];
            const float4* w4 = (const float4*)(wp + (c0 + c)*12);
#pragma unroll
            for (int o = 0; o < 3; o++) {
                float4 w = w4[o];
                acc[o] += i00*w.x + i01*w.y + i10*w.z + i11*w.w;
            }
        }
    }
#pragma unroll
    for (int o = 0; o < 3; o++) {
        float v = acc[o] + db[o];
        v = v / (1.f + __expf(-v));
        out[(((size_t)b*3 + o)*HIN + y)*WIN + x] = v;
    }
}

// ---------------------------------------------------------------------------
// Launch sequence
// ---------------------------------------------------------------------------
extern "C" void kernel_launch(void* const* d_in, const int* in_sizes, int n_in,
                              void* d_out, int out_size)
{
    const float* x      = (const float*)d_in[0];
    const float* e0n_w1 = (const float*)d_in[1];
    const float* e0n_b1 = (const float*)d_in[2];
    const float* e0n_w2 = (const float*)d_in[3];
    const float* e0n_b2 = (const float*)d_in[4];
    const float* e0s_w1 = (const float*)d_in[5];
    const float* e0s_b1 = (const float*)d_in[6];
    const float* e0s_w2 = (const float*)d_in[7];
    const float* e0s_b2 = (const float*)d_in[8];
    const float* d0_dw  = (const float*)d_in[9];
    const float* d0_db  = (const float*)d_in[10];
    const float* d0_cw  = (const float*)d_in[11];
    const float* d0_cb  = (const float*)d_in[12];
    const float* cell_k = (const float*)d_in[13];
    const float* cell_v = (const float*)d_in[14];
    float* outp = (float*)d_out;

    void *p_a1n, *p_a1s, *p_z, *p_ts, *p_w, *p_part, *p_gu, *p_vnew, *p_d0m, *p_dec;
    cudaGetSymbolAddress(&p_a1n, g_a1n);
    cudaGetSymbolAddress(&p_a1s, g_a1s);
    cudaGetSymbolAddress(&p_z,   g_z);
    cudaGetSymbolAddress(&p_ts,  g_ts);
    cudaGetSymbolAddress(&p_w,   g_w);
    cudaGetSymbolAddress(&p_part,g_part);
    cudaGetSymbolAddress(&p_gu,  g_gu);
    cudaGetSymbolAddress(&p_vnew,g_vnew);
    cudaGetSymbolAddress(&p_d0m, g_d0m);
    cudaGetSymbolAddress(&p_dec, g_dec);

    // Encoders
    convfast<3,16,1,false><<<dim3(8,8,Bb*2),256>>>(
        x, e0n_w1, e0n_b1, (float*)p_a1n, HIN, WIN, HIN, WIN);
    convfast<3,128,1,false><<<dim3(8,8,Bb*16),256>>>(
        x, e0s_w1, e0s_b1, (float*)p_a1s, HIN, WIN, HIN, WIN);
    convfast<16,16,2,true><<<dim3(4,4,Bb*2),256>>>(
        (const float*)p_a1n, e0n_w2, e0n_b2, (float*)p_z, HIN, WIN, H2, W2);
    convfast<128,128,2,true><<<dim3(4,4,Bb*16),256>>>(
        (const float*)p_a1s, e0s_w2, e0s_b2, (float*)p_ts, HIN, WIN, H2, W2);

    // Memcell
    memcell_softmax<<<Tt/256,256>>>((const float*)p_z, cell_k, (float*)p_w);
    memcell_outer<<<1024,256>>>((const float*)p_w, (const float*)p_ts, (float*)p_part);
    reduce_partials<<<20,256>>>((const float*)p_part, (float*)p_gu);
    cell_update<<<1,256>>>((const float*)p_gu, cell_v, (float*)p_vnew);
    memcell_read<<<Tt/64,256>>>((const float*)p_w, (const float*)p_vnew, (float*)p_d0m);

    // Decoder
    deconv_kernel<<<dim3(16,16,Bb),256>>>(
        (const float*)p_d0m, d0_dw, d0_db, (float*)p_dec);
    conv3x3<3,3,3,1,false><<<dim3(16,16,Bb),256>>>(
        (const float*)p_dec, d0_cw, d0_cb, outp, HIN, WIN, HIN, WIN);
}